// round 12
// baseline (speedup 1.0000x reference)
#include <cuda_runtime.h>
#include <cstdint>

#define B_  4
#define S_  2048
#define D_  1024
#define H_  16
#define DK  64

// Scratch in (b, h, s, d); g_Vt in (b, h, d, s)
__device__ float g_Q [(size_t)B_*H_*S_*DK];
__device__ float g_K [(size_t)B_*H_*S_*DK];
__device__ float g_V [(size_t)B_*H_*S_*DK];
__device__ float g_Vt[(size_t)B_*H_*S_*DK];

// Pre-split, pre-swizzled bf16 hi/lo tile images.
// X: 64 row-blocks x 128 k-slabs x (128 rows x 16 bf16) = 1024 u32/tile
__device__ uint32_t g_Xh[(size_t)64*128*1024];
__device__ uint32_t g_Xl[(size_t)64*128*1024];
// W: 3 matrices x 8 n-blocks x 128 k-slabs x 1024 u32
__device__ uint32_t g_Wh[(size_t)3*8*128*1024];
__device__ uint32_t g_Wl[(size_t)3*8*128*1024];

// ---------------------------------------------------------------------------
// Portable PTX helpers
// ---------------------------------------------------------------------------
__device__ __forceinline__ uint32_t smem_u32(const void* p) {
    uint32_t a;
    asm("{ .reg .u64 t; cvta.to.shared.u64 t, %1; cvt.u32.u64 %0, t; }"
        : "=r"(a) : "l"(p));
    return a;
}
__device__ __forceinline__ uint32_t tf32r(float f) {
    uint32_t u;
    asm("cvt.rna.tf32.f32 %0, %1;" : "=r"(u) : "f"(f));
    return u;
}
__device__ __forceinline__ void ldsm4(uint32_t r[4], uint32_t a) {
    asm volatile("ldmatrix.sync.aligned.m8n8.x4.shared.b16 {%0,%1,%2,%3}, [%4];"
        : "=r"(r[0]), "=r"(r[1]), "=r"(r[2]), "=r"(r[3]) : "r"(a));
}
// tf32 m16n8k8 (attention)
__device__ __forceinline__ void mma8(float* c, const uint32_t* a,
                                     uint32_t b0, uint32_t b1) {
    asm volatile("mma.sync.aligned.m16n8k8.row.col.f32.tf32.tf32.f32 "
        "{%0,%1,%2,%3}, {%4,%5,%6,%7}, {%8,%9}, {%0,%1,%2,%3};"
        : "+f"(c[0]), "+f"(c[1]), "+f"(c[2]), "+f"(c[3])
        : "r"(a[0]), "r"(a[1]), "r"(a[2]), "r"(a[3]), "r"(b0), "r"(b1));
}
// bf16 m16n8k16 (GEMM)
__device__ __forceinline__ void mma16(float* c, const uint32_t* a,
                                      uint32_t b0, uint32_t b1) {
    asm volatile("mma.sync.aligned.m16n8k16.row.col.f32.bf16.bf16.f32 "
        "{%0,%1,%2,%3}, {%4,%5,%6,%7}, {%8,%9}, {%0,%1,%2,%3};"
        : "+f"(c[0]), "+f"(c[1]), "+f"(c[2]), "+f"(c[3])
        : "r"(a[0]), "r"(a[1]), "r"(a[2]), "r"(a[3]), "r"(b0), "r"(b1));
}
// pack two floats to bf16x2: low half = lo, high half = hi
__device__ __forceinline__ uint32_t packbf(float lo, float hi) {
    uint32_t r;
    asm("cvt.rn.bf16x2.f32 %0, %1, %2;" : "=r"(r) : "f"(hi), "f"(lo));
    return r;
}
// split pair (f0,f1) into bf16 hi-pack and lo-pack
__device__ __forceinline__ void split2(float f0, float f1,
                                       uint32_t& h, uint32_t& l) {
    h = packbf(f0, f1);
    float h0 = __uint_as_float(h << 16);
    float h1 = __uint_as_float(h & 0xffff0000u);
    l = packbf(f0 - h0, f1 - h1);
}
__device__ __forceinline__ void cp_async16(uint32_t s, const void* g) {
    asm volatile("cp.async.cg.shared.global [%0], [%1], 16;" :: "r"(s), "l"(g));
}
#define CP_COMMIT() asm volatile("cp.async.commit_group;" ::: "memory")
#define CP_WAIT(n)  asm volatile("cp.async.wait_group %0;" :: "n"(n) : "memory")

#define SWZ64(row, q) (((q) & 8) | ((((q) ^ ((row) & 7) ^ (((row) >> 3) & 7))) & 7))

// ---------------------------------------------------------------------------
// prep_split: fp32 (src_s | src_t along k) -> bf16 hi/lo smem tile images.
// ---------------------------------------------------------------------------
__global__ __launch_bounds__(256) void prep_split(
    const float* __restrict__ src_s, const float* __restrict__ src_t,
    uint32_t* __restrict__ dh, uint32_t* __restrict__ dl)
{
    const int rb = blockIdx.x, slab = blockIdx.y;   // slab 0..127
    const int t = threadIdx.x;
    const int row = t >> 1, half = t & 1;
    const float* src = (slab & 64) ? src_t : src_s;
    const float* p = src + (size_t)(rb * 128 + row) * 1024 + (slab & 63) * 16 + half * 8;
    float4 v0 = *(const float4*)p;
    float4 v1 = *(const float4*)(p + 4);
    uint32_t h[4], l[4];
    split2(v0.x, v0.y, h[0], l[0]); split2(v0.z, v0.w, h[1], l[1]);
    split2(v1.x, v1.y, h[2], l[2]); split2(v1.z, v1.w, h[3], l[3]);
    const size_t tile = ((size_t)rb * 128 + slab) * 1024;
    const int off = row * 8 + ((half ^ ((row >> 2) & 1)) * 4);   // u32 units
    *(uint4*)&dh[tile + off] = make_uint4(h[0], h[1], h[2], h[3]);
    *(uint4*)&dl[tile + off] = make_uint4(l[0], l[1], l[2], l[3]);
}

// ---------------------------------------------------------------------------
// QKV dual-linear GEMM, 3-term BF16, block tile 128x256, 8 warps (64x64).
// 4-stage cp.async pipeline; dynamic smem 96KB; 1 CTA/SM.
// Stage layout (u32): AH[1024] AL[1024] BH[2048] BL[2048] = 6144 per stage.
// ---------------------------------------------------------------------------
__global__ __launch_bounds__(256, 1) void qkv_gemm_v11(
    const float* __restrict__ bqs, const float* __restrict__ bqt,
    const float* __restrict__ bks, const float* __restrict__ bkt,
    const float* __restrict__ bvs, const float* __restrict__ bvt)
{
    extern __shared__ uint32_t gsm[];

    const int tid = threadIdx.x;
    const int lane = tid & 31;
    const int wid = tid >> 5;
    const int wr = wid >> 2;          // 0..1 (64-row strips)
    const int wc = wid & 3;           // 0..3 (64-col strips)

    const int bm = blockIdx.x;
    const int bn = blockIdx.y;        // 0..11
    const int mi = bn >> 2;           // 0=Q,1=K,2=V
    const int n0 = (bn & 3) * 256;
    const int m0 = bm * 128;

    const float* bsp = (mi == 0) ? bqs : (mi == 1) ? bks : bvs;
    const float* btp = (mi == 0) ? bqt : (mi == 1) ? bkt : bvt;
    float* Out = (mi == 0) ? g_Q : (mi == 1) ? g_K : g_V;

    const uint32_t* Ah_g = g_Xh + (size_t)bm * 131072;   // 128 tiles x 1024
    const uint32_t* Al_g = g_Xl + (size_t)bm * 131072;
    const size_t wb0 = ((size_t)mi * 8 + 2 * (bn & 3)) * 131072;
    const uint32_t* Bh0 = g_Wh + wb0;
    const uint32_t* Bl0 = g_Wl + wb0;
    const uint32_t* Bh1 = Bh0 + 131072;   // next 128-row n-block
    const uint32_t* Bl1 = Bl0 + 131072;

    float acc[4][8][4];
    #pragma unroll
    for (int mt = 0; mt < 4; mt++)
        #pragma unroll
        for (int nt = 0; nt < 8; nt++)
            #pragma unroll
            for (int r = 0; r < 4; r++) acc[mt][nt][r] = 0.f;

    const int t4 = tid * 4;

    // consumer mapping
    const int l15 = lane & 15;
    const int qsw = (((lane >> 4) ^ ((l15 >> 2) & 1))) * 16;
    const int aRowOff = (wr * 64 + l15) * 32 + qsw;   // bytes, + mt*512
    const int bRowOff = (wc * 64 + l15) * 32 + qsw;   // bytes, + half*512

    // ---- prologue: stages 0..2 ----
    #pragma unroll
    for (int s = 0; s < 3; s++) {
        uint32_t st = smem_u32(gsm + s * 6144);
        const int g = s * 1024 + t4;
        cp_async16(st + t4 * 4,              Ah_g + g);
        cp_async16(st + (1024 + t4) * 4,     Al_g + g);
        cp_async16(st + (2048 + t4) * 4,     Bh0 + g);
        cp_async16(st + (3072 + t4) * 4,     Bh1 + g);
        cp_async16(st + (4096 + t4) * 4,     Bl0 + g);
        cp_async16(st + (5120 + t4) * 4,     Bl1 + g);
        CP_COMMIT();
    }

    #pragma unroll 1
    for (int it = 0; it < 128; it++) {
        if (it < 126) { CP_WAIT(2); } else if (it == 126) { CP_WAIT(1); }
        else { CP_WAIT(0); }
        __syncthreads();   // stage(it) fully visible; stage buf (it+3)%4 free

        if (it < 125) {
            uint32_t st = smem_u32(gsm + ((it + 3) & 3) * 6144);
            const int g = (it + 3) * 1024 + t4;
            cp_async16(st + t4 * 4,          Ah_g + g);
            cp_async16(st + (1024 + t4) * 4, Al_g + g);
            cp_async16(st + (2048 + t4) * 4, Bh0 + g);
            cp_async16(st + (3072 + t4) * 4, Bh1 + g);
            cp_async16(st + (4096 + t4) * 4, Bl0 + g);
            cp_async16(st + (5120 + t4) * 4, Bl1 + g);
            CP_COMMIT();
        }

        const uint32_t sb = smem_u32(gsm + (it & 3) * 6144);
        const uint32_t aH = sb;
        const uint32_t aL = sb + 4096;
        const uint32_t bH = sb + 8192;
        const uint32_t bL = sb + 16384;

        uint32_t fAh[4][4], fAl[4][4];
        #pragma unroll
        for (int mt = 0; mt < 4; mt++) {
            ldsm4(fAh[mt], aH + aRowOff + mt * 512);
            ldsm4(fAl[mt], aL + aRowOff + mt * 512);
        }
        #pragma unroll
        for (int half = 0; half < 4; half++) {
            uint32_t fBh[4], fBl[4];
            ldsm4(fBh, bH + bRowOff + half * 512);
            ldsm4(fBl, bL + bRowOff + half * 512);
            #pragma unroll
            for (int n2 = 0; n2 < 2; n2++) {
                const int nt = half * 2 + n2;
                #pragma unroll
                for (int mt = 0; mt < 4; mt++) {
                    mma16(acc[mt][nt], fAh[mt], fBh[n2], fBh[n2 + 2]);
                    mma16(acc[mt][nt], fAl[mt], fBh[n2], fBh[n2 + 2]);
                    mma16(acc[mt][nt], fAh[mt], fBl[n2], fBl[n2 + 2]);
                }
            }
        }
    }

    // Epilogue: add biases, round to tf32 (attention consumes as mma inputs)
    const int r4 = lane >> 2;
    const int q2 = (lane & 3) * 2;
    #pragma unroll
    for (int mt = 0; mt < 4; mt++) {
        const int t = m0 + wr * 64 + mt * 16 + r4;
        #pragma unroll
        for (int nt = 0; nt < 8; nt++) {
            const int c0 = n0 + wc * 64 + nt * 8 + q2;
            const float bx = bsp[c0] + btp[c0];
            const float by = bsp[c0 + 1] + btp[c0 + 1];
            const int h = c0 >> 6, d = c0 & 63;
            #pragma unroll
            for (int half = 0; half < 2; half++) {
                const int tt = t + half * 8;
                const int bb = tt >> 11;
                const int ss = tt & 2047;
                float2 v;
                v.x = __uint_as_float(tf32r(acc[mt][nt][half * 2 + 0] + bx));
                v.y = __uint_as_float(tf32r(acc[mt][nt][half * 2 + 1] + by));
                *(float2*)&Out[(((size_t)(bb * H_ + h)) * S_ + ss) * DK + d] = v;
            }
        }
    }
}

// ---------------------------------------------------------------------------
// V transpose: g_V (bh, s, d) -> g_Vt (bh, d, s)
// ---------------------------------------------------------------------------
__global__ __launch_bounds__(256) void vtrans() {
    __shared__ float T[64][65];
    const int bh = blockIdx.y;
    const int sc = blockIdx.x;
    const float* src = g_V + ((size_t)bh * S_ + sc * 64) * DK;
    #pragma unroll
    for (int i = 0; i < 16; i++) {
        int idx = threadIdx.x + 256 * i;
        T[idx >> 6][idx & 63] = src[idx];
    }
    __syncthreads();
    float* dst = g_Vt + (size_t)bh * DK * S_ + sc * 64;
    #pragma unroll
    for (int i = 0; i < 16; i++) {
        int idx = threadIdx.x + 256 * i;
        int d = idx >> 6, s = idx & 63;
        dst[(size_t)d * S_ + s] = T[s][d];
    }
}

// ---------------------------------------------------------------------------
// Flash attention (tf32 mma.sync). BQ=128 (8 warps x 16 rows), BK=64.
// Q fragments hoisted to registers; ONE __syncthreads per chunk.
// ---------------------------------------------------------------------------
__global__ __launch_bounds__(256) void attn_mma(
    const float* __restrict__ bias_p, float* __restrict__ out)
{
    extern __shared__ uint32_t asm_[];
    const uint32_t base = smem_u32(asm_);
    const uint32_t smQ = base;
    const uint32_t smP = base + 98304;

    const int tid = threadIdx.x;
    const int lane = tid & 31;
    const int wid = tid >> 5;

    const int qt = blockIdx.x;
    const int bh = blockIdx.y;
    const int q0 = qt * 128;
    const float* Q  = g_Q  + (size_t)bh * S_ * DK;
    const float* K  = g_K  + (size_t)bh * S_ * DK;
    const float* Vt = g_Vt + (size_t)bh * S_ * DK;   // (d, s)
    const float cb = bias_p[0];
    const float SC = 0.125f;

    // ---- prologue: Q + chunk0 via cp.async (one group) ----
    #pragma unroll
    for (int i = 0; i < 8; i++) {
        int idx = tid + 256 * i;
        int row = idx >> 4, q = idx & 15;
        cp_async16(smQ + (row * 64 + SWZ64(row, q) * 4) * 4,
                   Q + (size_t)(q0 + row) * DK + q * 4);
    }
    #pragma unroll
    for (int i = 0; i < 4; i++) {
        int idx = tid + 256 * i;
        int row = idx >> 4, q = idx & 15;
        cp_async16(base + 32768 + (row * 64 + SWZ64(row, q) * 4) * 4,
                   K + (size_t)row * DK + q * 4);
        cp_async16(base + 65536 + (row * 64 + SWZ64(row, q) * 4) * 4,
                   Vt + (size_t)row * S_ + q * 4);
    }
    CP_COMMIT();

    const int arow = wid * 16 + (lane & 15);
    const int aqh = lane >> 4;
    const int b8 = lane & 7;
    const int bqh = lane >> 3;
    const int r4 = lane >> 2;
    const int q2 = (lane & 3) * 2;

    CP_WAIT(0);
    __syncthreads();

    // ---- hoist Q fragments (loop-invariant) ----
    uint32_t fQ0[4][4], fQ1[4][4];
    #pragma unroll
    for (int p = 0; p < 4; p++) {
        ldsm4(fQ0[p], smQ + arow * 256 + SWZ64(arow, 4 * p + aqh) * 16);
        ldsm4(fQ1[p], smQ + arow * 256 + SWZ64(arow, 4 * p + 2 + aqh) * 16);
    }

    float o[8][4];
    #pragma unroll
    for (int nt = 0; nt < 8; nt++)
        #pragma unroll
        for (int r = 0; r < 4; r++) o[nt][r] = 0.f;
    float m0r = -1e30f, m1r = -1e30f, l0 = 0.f, l1 = 0.f;

    #pragma unroll 1
    for (int kc = 0; kc < 32; kc++) {
        const int buf = kc & 1;
        // prefetch next chunk into the buffer freed by chunk kc-1
        if (kc < 31) {
            const int nb = (kc + 1) & 1;
            const int k0 = (kc + 1) * 64;
            #pragma unroll
            for (int i = 0; i < 4; i++) {
                int idx = tid + 256 * i;
                int row = idx >> 4, q = idx & 15;
                cp_async16(base + 32768 + nb * 16384 + (row * 64 + SWZ64(row, q) * 4) * 4,
                           K + (size_t)(k0 + row) * DK + q * 4);
                cp_async16(base + 65536 + nb * 16384 + (row * 64 + SWZ64(row, q) * 4) * 4,
                           Vt + (size_t)row * S_ + k0 + q * 4);
            }
            CP_COMMIT();
        }

        const uint32_t smK = base + 32768 + buf * 16384;
        const uint32_t smV = base + 65536 + buf * 16384;

        // ---- S = Q K^T ----
        float s[8][4];
        #pragma unroll
        for (int nt = 0; nt < 8; nt++)
            #pragma unroll
            for (int r = 0; r < 4; r++) s[nt][r] = 0.f;

        #pragma unroll
        for (int p = 0; p < 4; p++) {
            #pragma unroll
            for (int nt = 0; nt < 8; nt++) {
                const int row = nt * 8 + b8;
                uint32_t bf[4];
                ldsm4(bf, smK + row * 256 + SWZ64(row, 4 * p + bqh) * 16);
                mma8(s[nt], fQ0[p], bf[0], bf[1]);
                mma8(s[nt], fQ1[p], bf[2], bf[3]);
            }
        }

        // ---- online softmax ----
        float mx0 = -1e30f, mx1 = -1e30f;
        #pragma unroll
        for (int nt = 0; nt < 8; nt++) {
            mx0 = fmaxf(mx0, fmaxf(s[nt][0], s[nt][1]));
            mx1 = fmaxf(mx1, fmaxf(s[nt][2], s[nt][3]));
        }
        mx0 = fmaxf(mx0, __shfl_xor_sync(0xffffffffu, mx0, 1));
        mx0 = fmaxf(mx0, __shfl_xor_sync(0xffffffffu, mx0, 2));
        mx1 = fmaxf(mx1, __shfl_xor_sync(0xffffffffu, mx1, 1));
        mx1 = fmaxf(mx1, __shfl_xor_sync(0xffffffffu, mx1, 2));

        const float mn0 = fmaxf(m0r, mx0 * SC + cb);
        const float mn1 = fmaxf(m1r, mx1 * SC + cb);
        const float rs0 = __expf(m0r - mn0);
        const float rs1 = __expf(m1r - mn1);
        m0r = mn0; m1r = mn1;

        const int row0 = wid * 16 + r4;
        const int row1 = row0 + 8;
        float sum0 = 0.f, sum1 = 0.f;
        #pragma unroll
        for (int nt = 0; nt < 8; nt++) {
            uint32_t p00 = tf32r(__expf(s[nt][0] * SC + cb - mn0));
            uint32_t p01 = tf32r(__expf(s[nt][1] * SC + cb - mn0));
            uint32_t p10 = tf32r(__expf(s[nt][2] * SC + cb - mn1));
            uint32_t p11 = tf32r(__expf(s[nt][3] * SC + cb - mn1));
            sum0 += __uint_as_float(p00) + __uint_as_float(p01);
            sum1 += __uint_as_float(p10) + __uint_as_float(p11);
            const int qd = nt * 2 + (q2 >> 2);
            const int i0 = row0 * 64 + SWZ64(row0, qd) * 4 + (q2 & 3);
            const int i1 = row1 * 64 + SWZ64(row1, qd) * 4 + (q2 & 3);
            *(uint2*)&asm_[24576 + i0] = make_uint2(p00, p01);
            *(uint2*)&asm_[24576 + i1] = make_uint2(p10, p11);
        }
        sum0 += __shfl_xor_sync(0xffffffffu, sum0, 1);
        sum0 += __shfl_xor_sync(0xffffffffu, sum0, 2);
        sum1 += __shfl_xor_sync(0xffffffffu, sum1, 1);
        sum1 += __shfl_xor_sync(0xffffffffu, sum1, 2);
        l0 = l0 * rs0 + sum0;
        l1 = l1 * rs1 + sum1;

        #pragma unroll
        for (int nt = 0; nt < 8; nt++) {
            o[nt][0] *= rs0; o[nt][1] *= rs0;
            o[nt][2] *= rs1; o[nt][3] *= rs1;
        }
        __syncwarp();   // P rows are warp-private; warp-level ordering suffices

        // ---- O += P V ----
        #pragma unroll
        for (int p = 0; p < 4; p++) {
            uint32_t af0[4], af1[4];
            ldsm4(af0, smP + arow * 256 + SWZ64(arow, 4 * p + aqh) * 16);
            ldsm4(af1, smP + arow * 256 + SWZ64(arow, 4 * p + 2 + aqh) * 16);
            #pragma unroll
            for (int nt = 0; nt < 8; nt++) {
                const int row = nt * 8 + b8;   // d index
                uint32_t bf[4];
                ldsm4(bf, smV + row * 256 + SWZ64(row, 4 * p + bqh) * 16);
                mma8(o[nt], af0, bf[0], bf[1]);
                mma8(o[nt], af1, bf[2], bf[3]);
            }
        }

        // prefetched chunk ready + all warps done with buf kc&1
        if (kc < 31) {
            CP_WAIT(0);
            __syncthreads();
        }
    }

    // ---- normalize + write out (b, s, h*64+d) ----
    const float inv0 = 1.f / l0;
    const float inv1 = 1.f / l1;
    const int bb = bh >> 4, hh = bh & 15;
    const int gq0 = q0 + wid * 16 + r4;
    float* op0 = out + ((size_t)(bb * S_ + gq0)) * D_ + hh * DK;
    float* op1 = out + ((size_t)(bb * S_ + gq0 + 8)) * D_ + hh * DK;
    #pragma unroll
    for (int nt = 0; nt < 8; nt++) {
        const int d = nt * 8 + q2;
        float2 v0, v1;
        v0.x = o[nt][0] * inv0; v0.y = o[nt][1] * inv0;
        v1.x = o[nt][2] * inv1; v1.y = o[nt][3] * inv1;
        *(float2*)&op0[d] = v0;
        *(float2*)&op1[d] = v1;
    }
}

// ---------------------------------------------------------------------------
extern "C" void kernel_launch(void* const* d_in, const int* in_sizes, int n_in,
                              void* d_out, int out_size)
{
    const float* Xs  = (const float*)d_in[0];
    const float* Xt  = (const float*)d_in[1];
    const float* Wqs = (const float*)d_in[2];
    const float* bqs = (const float*)d_in[3];
    const float* Wqt = (const float*)d_in[4];
    const float* bqt = (const float*)d_in[5];
    const float* Wks = (const float*)d_in[6];
    const float* bks = (const float*)d_in[7];
    const float* Wkt = (const float*)d_in[8];
    const float* bkt = (const float*)d_in[9];
    const float* Wvs = (const float*)d_in[10];
    const float* bvs = (const float*)d_in[11];
    const float* Wvt = (const float*)d_in[12];
    const float* bvt = (const float*)d_in[13];
    const float* attn_bias = (const float*)d_in[14];
    float* out = (float*)d_out;

    cudaFuncSetAttribute(attn_mma,
        cudaFuncAttributeMaxDynamicSharedMemorySize, 131072);
    cudaFuncSetAttribute(qkv_gemm_v11,
        cudaFuncAttributeMaxDynamicSharedMemorySize, 98304);

    uint32_t* Xh; uint32_t* Xl; uint32_t* Wh; uint32_t* Wl;
    cudaGetSymbolAddress((void**)&Xh, g_Xh);
    cudaGetSymbolAddress((void**)&Xl, g_Xl);
    cudaGetSymbolAddress((void**)&Wh, g_Wh);
    cudaGetSymbolAddress((void**)&Wl, g_Wl);

    // prep: split + pre-swizzle (X: 64 row-blocks; each W pair: 8 n-blocks)
    prep_split<<<dim3(64, 128), 256>>>(Xs, Xt, Xh, Xl);
    prep_split<<<dim3(8, 128), 256>>>(Wqs, Wqt, Wh, Wl);
    prep_split<<<dim3(8, 128), 256>>>(Wks, Wkt, Wh + 1048576, Wl + 1048576);
    prep_split<<<dim3(8, 128), 256>>>(Wvs, Wvt, Wh + 2097152, Wl + 2097152);

    dim3 gGrid(64, 12);
    qkv_gemm_v11<<<gGrid, 256, 98304>>>(bqs, bqt, bks, bkt, bvs, bvt);

    dim3 tGrid(32, B_ * H_);
    vtrans<<<tGrid, 256>>>();

    dim3 aGrid(16, B_ * H_);
    attn_mma<<<aGrid, 256, 131072>>>(attn_bias, out);
}

// round 13
// speedup vs baseline: 1.0847x; 1.0847x over previous
#include <cuda_runtime.h>
#include <cstdint>

#define B_  4
#define S_  2048
#define D_  1024
#define H_  16
#define DK  64

// Scratch in (b, h, s, d); g_Vt in (b, h, d, s)
__device__ float g_Q [(size_t)B_*H_*S_*DK];
__device__ float g_K [(size_t)B_*H_*S_*DK];
__device__ float g_V [(size_t)B_*H_*S_*DK];
__device__ float g_Vt[(size_t)B_*H_*S_*DK];

// Pre-split, pre-swizzled bf16 hi/lo tile images.
__device__ uint32_t g_Xh[(size_t)64*128*1024];
__device__ uint32_t g_Xl[(size_t)64*128*1024];
__device__ uint32_t g_Wh[(size_t)3*8*128*1024];
__device__ uint32_t g_Wl[(size_t)3*8*128*1024];

// ---------------------------------------------------------------------------
// Portable PTX helpers
// ---------------------------------------------------------------------------
__device__ __forceinline__ uint32_t smem_u32(const void* p) {
    uint32_t a;
    asm("{ .reg .u64 t; cvta.to.shared.u64 t, %1; cvt.u32.u64 %0, t; }"
        : "=r"(a) : "l"(p));
    return a;
}
__device__ __forceinline__ uint32_t tf32r(float f) {
    uint32_t u;
    asm("cvt.rna.tf32.f32 %0, %1;" : "=r"(u) : "f"(f));
    return u;
}
__device__ __forceinline__ void ldsm4(uint32_t r[4], uint32_t a) {
    asm volatile("ldmatrix.sync.aligned.m8n8.x4.shared.b16 {%0,%1,%2,%3}, [%4];"
        : "=r"(r[0]), "=r"(r[1]), "=r"(r[2]), "=r"(r[3]) : "r"(a));
}
// tf32 m16n8k8 (attention)
__device__ __forceinline__ void mma8(float* c, const uint32_t* a,
                                     uint32_t b0, uint32_t b1) {
    asm volatile("mma.sync.aligned.m16n8k8.row.col.f32.tf32.tf32.f32 "
        "{%0,%1,%2,%3}, {%4,%5,%6,%7}, {%8,%9}, {%0,%1,%2,%3};"
        : "+f"(c[0]), "+f"(c[1]), "+f"(c[2]), "+f"(c[3])
        : "r"(a[0]), "r"(a[1]), "r"(a[2]), "r"(a[3]), "r"(b0), "r"(b1));
}
// bf16 m16n8k16 (GEMM)
__device__ __forceinline__ void mma16(float* c, const uint32_t* a,
                                      uint32_t b0, uint32_t b1) {
    asm volatile("mma.sync.aligned.m16n8k16.row.col.f32.bf16.bf16.f32 "
        "{%0,%1,%2,%3}, {%4,%5,%6,%7}, {%8,%9}, {%0,%1,%2,%3};"
        : "+f"(c[0]), "+f"(c[1]), "+f"(c[2]), "+f"(c[3])
        : "r"(a[0]), "r"(a[1]), "r"(a[2]), "r"(a[3]), "r"(b0), "r"(b1));
}
__device__ __forceinline__ uint32_t packbf(float lo, float hi) {
    uint32_t r;
    asm("cvt.rn.bf16x2.f32 %0, %1, %2;" : "=r"(r) : "f"(hi), "f"(lo));
    return r;
}
__device__ __forceinline__ void split2(float f0, float f1,
                                       uint32_t& h, uint32_t& l) {
    h = packbf(f0, f1);
    float h0 = __uint_as_float(h << 16);
    float h1 = __uint_as_float(h & 0xffff0000u);
    l = packbf(f0 - h0, f1 - h1);
}
__device__ __forceinline__ void cp_async16(uint32_t s, const void* g) {
    asm volatile("cp.async.cg.shared.global [%0], [%1], 16;" :: "r"(s), "l"(g));
}
#define CP_COMMIT() asm volatile("cp.async.commit_group;" ::: "memory")
#define CP_WAIT(n)  asm volatile("cp.async.wait_group %0;" :: "n"(n) : "memory")

#define SWZ64(row, q) (((q) & 8) | ((((q) ^ ((row) & 7) ^ (((row) >> 3) & 7))) & 7))

// ---------------------------------------------------------------------------
// prep_split: fp32 (src_s | src_t along k) -> bf16 hi/lo tile images.
// ---------------------------------------------------------------------------
__global__ __launch_bounds__(256) void prep_split(
    const float* __restrict__ src_s, const float* __restrict__ src_t,
    uint32_t* __restrict__ dh, uint32_t* __restrict__ dl)
{
    const int rb = blockIdx.x, slab = blockIdx.y;   // slab 0..127
    const int t = threadIdx.x;
    const int row = t >> 1, half = t & 1;
    const float* src = (slab & 64) ? src_t : src_s;
    const float* p = src + (size_t)(rb * 128 + row) * 1024 + (slab & 63) * 16 + half * 8;
    float4 v0 = *(const float4*)p;
    float4 v1 = *(const float4*)(p + 4);
    uint32_t h[4], l[4];
    split2(v0.x, v0.y, h[0], l[0]); split2(v0.z, v0.w, h[1], l[1]);
    split2(v1.x, v1.y, h[2], l[2]); split2(v1.z, v1.w, h[3], l[3]);
    const size_t tile = ((size_t)rb * 128 + slab) * 1024;
    const int off = row * 8 + ((half ^ ((row >> 2) & 1)) * 4);   // u32 units
    *(uint4*)&dh[tile + off] = make_uint4(h[0], h[1], h[2], h[3]);
    *(uint4*)&dl[tile + off] = make_uint4(l[0], l[1], l[2], l[3]);
}

// ---------------------------------------------------------------------------
// QKV dual-linear GEMM, 3-term BF16, consuming pre-split tile images (v10).
// Block 128x128, BK=16, 8 warps (64x32 each), 2 CTAs/SM (48KB smem).
// ---------------------------------------------------------------------------
__global__ __launch_bounds__(256, 2) void qkv_gemm_v10(
    const float* __restrict__ bqs, const float* __restrict__ bqt,
    const float* __restrict__ bks, const float* __restrict__ bkt,
    const float* __restrict__ bvs, const float* __restrict__ bvt)
{
    __shared__ uint32_t AH[3][1024], AL[3][1024], BH[3][1024], BL[3][1024];

    const int tid = threadIdx.x;
    const int lane = tid & 31;
    const int wid = tid >> 5;
    const int wr = wid >> 2;
    const int wc = wid & 3;

    const int bm = blockIdx.x;
    const int bn = blockIdx.y;
    const int mi = bn >> 3;
    const int n0 = (bn & 7) * 128;
    const int m0 = bm * 128;

    const float* bsp = (mi == 0) ? bqs : (mi == 1) ? bks : bvs;
    const float* btp = (mi == 0) ? bqt : (mi == 1) ? bkt : bvt;
    float* Out = (mi == 0) ? g_Q : (mi == 1) ? g_K : g_V;

    const uint32_t* Ah_g = g_Xh + (size_t)bm * 131072;
    const uint32_t* Al_g = g_Xl + (size_t)bm * 131072;
    const size_t wbase = ((size_t)mi * 8 + (bn & 7)) * 131072;
    const uint32_t* Bh_g = g_Wh + wbase;
    const uint32_t* Bl_g = g_Wl + wbase;

    float acc[4][4][4];
    #pragma unroll
    for (int mt = 0; mt < 4; mt++)
        #pragma unroll
        for (int nt = 0; nt < 4; nt++)
            #pragma unroll
            for (int r = 0; r < 4; r++) acc[mt][nt][r] = 0.f;

    const int t4 = tid * 4;

    const int l15 = lane & 15;
    const int qsw = (((lane >> 4) ^ ((l15 >> 2) & 1))) * 16;
    const int aRowOff = (wr * 64 + l15) * 32 + qsw;
    const int bRowOff = (wc * 32 + l15) * 32 + qsw;

    #pragma unroll
    for (int s = 0; s < 2; s++) {
        cp_async16(smem_u32(&AH[s][t4]), Ah_g + s * 1024 + t4);
        cp_async16(smem_u32(&AL[s][t4]), Al_g + s * 1024 + t4);
        cp_async16(smem_u32(&BH[s][t4]), Bh_g + s * 1024 + t4);
        cp_async16(smem_u32(&BL[s][t4]), Bl_g + s * 1024 + t4);
        CP_COMMIT();
    }

    int buf = 0;
    #pragma unroll 1
    for (int it = 0; it < 128; it++) {
        if (it < 127) { CP_WAIT(1); } else { CP_WAIT(0); }
        __syncthreads();

        if (it < 126) {
            const int st = (buf + 2 >= 3) ? (buf - 1) : (buf + 2);
            const int nt2 = (it + 2) * 1024 + t4;
            cp_async16(smem_u32(&AH[st][t4]), Ah_g + nt2);
            cp_async16(smem_u32(&AL[st][t4]), Al_g + nt2);
            cp_async16(smem_u32(&BH[st][t4]), Bh_g + nt2);
            cp_async16(smem_u32(&BL[st][t4]), Bl_g + nt2);
            CP_COMMIT();
        }

        const uint32_t aH = smem_u32(&AH[buf][0]);
        const uint32_t aL = smem_u32(&AL[buf][0]);
        const uint32_t bH = smem_u32(&BH[buf][0]);
        const uint32_t bL = smem_u32(&BL[buf][0]);

        uint32_t fAh[4][4], fAl[4][4];
        #pragma unroll
        for (int mt = 0; mt < 4; mt++) {
            ldsm4(fAh[mt], aH + aRowOff + mt * 512);
            ldsm4(fAl[mt], aL + aRowOff + mt * 512);
        }
        #pragma unroll
        for (int half = 0; half < 2; half++) {
            uint32_t fBh[4], fBl[4];
            ldsm4(fBh, bH + bRowOff + half * 512);
            ldsm4(fBl, bL + bRowOff + half * 512);
            #pragma unroll
            for (int n2 = 0; n2 < 2; n2++) {
                const int nt = half * 2 + n2;
                #pragma unroll
                for (int mt = 0; mt < 4; mt++) {
                    mma16(acc[mt][nt], fAh[mt], fBh[n2], fBh[n2 + 2]);
                    mma16(acc[mt][nt], fAl[mt], fBh[n2], fBh[n2 + 2]);
                    mma16(acc[mt][nt], fAh[mt], fBl[n2], fBl[n2 + 2]);
                }
            }
        }
        buf = (buf == 2) ? 0 : (buf + 1);
    }

    const int r4 = lane >> 2;
    const int q2 = (lane & 3) * 2;
    #pragma unroll
    for (int mt = 0; mt < 4; mt++) {
        const int t = m0 + wr * 64 + mt * 16 + r4;
        #pragma unroll
        for (int nt = 0; nt < 4; nt++) {
            const int c0 = n0 + wc * 32 + nt * 8 + q2;
            const float bx = bsp[c0] + btp[c0];
            const float by = bsp[c0 + 1] + btp[c0 + 1];
            const int h = c0 >> 6, d = c0 & 63;
            #pragma unroll
            for (int half = 0; half < 2; half++) {
                const int tt = t + half * 8;
                const int bb = tt >> 11;
                const int ss = tt & 2047;
                float2 v;
                v.x = __uint_as_float(tf32r(acc[mt][nt][half * 2 + 0] + bx));
                v.y = __uint_as_float(tf32r(acc[mt][nt][half * 2 + 1] + by));
                *(float2*)&Out[(((size_t)(bb * H_ + h)) * S_ + ss) * DK + d] = v;
            }
        }
    }
}

// ---------------------------------------------------------------------------
// V transpose: g_V (bh, s, d) -> g_Vt (bh, d, s)
// ---------------------------------------------------------------------------
__global__ __launch_bounds__(256) void vtrans() {
    __shared__ float T[64][65];
    const int bh = blockIdx.y;
    const int sc = blockIdx.x;
    const float* src = g_V + ((size_t)bh * S_ + sc * 64) * DK;
    #pragma unroll
    for (int i = 0; i < 16; i++) {
        int idx = threadIdx.x + 256 * i;
        T[idx >> 6][idx & 63] = src[idx];
    }
    __syncthreads();
    float* dst = g_Vt + (size_t)bh * DK * S_ + sc * 64;
    #pragma unroll
    for (int i = 0; i < 16; i++) {
        int idx = threadIdx.x + 256 * i;
        int d = idx >> 6, s = idx & 63;
        dst[(size_t)d * S_ + s] = T[s][d];
    }
}

// ---------------------------------------------------------------------------
// Flash attention (tf32 mma.sync). BQ=256 (16 warps x 16 rows), BK=64.
// 512 threads, 1 CTA/SM, smem 192KB:
//   Q [0,64K), K 2x16K at 64K, Vt 2x16K at 96K, P [128K,192K).
// Per-warp math identical to v10 (16 q-rows/warp) -> bit-identical numerics.
// ---------------------------------------------------------------------------
__global__ __launch_bounds__(512, 1) void attn_mma(
    const float* __restrict__ bias_p, float* __restrict__ out)
{
    extern __shared__ uint32_t asm_[];
    const uint32_t base = smem_u32(asm_);
    const uint32_t smQ = base;
    const uint32_t smP = base + 131072;

    const int tid = threadIdx.x;
    const int lane = tid & 31;
    const int wid = tid >> 5;          // 0..15

    const int qt = blockIdx.x;         // 0..7
    const int bh = blockIdx.y;         // 0..63
    const int q0 = qt * 256;
    const float* Q  = g_Q  + (size_t)bh * S_ * DK;
    const float* K  = g_K  + (size_t)bh * S_ * DK;
    const float* Vt = g_Vt + (size_t)bh * S_ * DK;   // (d, s)
    const float cb = bias_p[0];
    const float SC = 0.125f;

    // ---- prologue: Q (256 rows) + chunk0 via cp.async ----
    #pragma unroll
    for (int i = 0; i < 8; i++) {
        int idx = tid + 512 * i;
        int row = idx >> 4, q = idx & 15;
        cp_async16(smQ + (row * 64 + SWZ64(row, q) * 4) * 4,
                   Q + (size_t)(q0 + row) * DK + q * 4);
    }
    #pragma unroll
    for (int i = 0; i < 2; i++) {
        int idx = tid + 512 * i;
        int row = idx >> 4, q = idx & 15;
        cp_async16(base + 65536 + (row * 64 + SWZ64(row, q) * 4) * 4,
                   K + (size_t)row * DK + q * 4);
        cp_async16(base + 98304 + (row * 64 + SWZ64(row, q) * 4) * 4,
                   Vt + (size_t)row * S_ + q * 4);
    }
    CP_COMMIT();

    const int arow = wid * 16 + (lane & 15);
    const int aqh = lane >> 4;
    const int b8 = lane & 7;
    const int bqh = lane >> 3;
    const int r4 = lane >> 2;
    const int q2 = (lane & 3) * 2;

    CP_WAIT(0);
    __syncthreads();

    float o[8][4];
    #pragma unroll
    for (int nt = 0; nt < 8; nt++)
        #pragma unroll
        for (int r = 0; r < 4; r++) o[nt][r] = 0.f;
    float m0r = -1e30f, m1r = -1e30f, l0 = 0.f, l1 = 0.f;

    #pragma unroll 1
    for (int kc = 0; kc < 32; kc++) {
        const int buf = kc & 1;
        if (kc < 31) {
            const int nb = (kc + 1) & 1;
            const int k0 = (kc + 1) * 64;
            #pragma unroll
            for (int i = 0; i < 2; i++) {
                int idx = tid + 512 * i;
                int row = idx >> 4, q = idx & 15;
                cp_async16(base + 65536 + nb * 16384 + (row * 64 + SWZ64(row, q) * 4) * 4,
                           K + (size_t)(k0 + row) * DK + q * 4);
                cp_async16(base + 98304 + nb * 16384 + (row * 64 + SWZ64(row, q) * 4) * 4,
                           Vt + (size_t)row * S_ + k0 + q * 4);
            }
            CP_COMMIT();
        }

        const uint32_t smK = base + 65536 + buf * 16384;
        const uint32_t smV = base + 98304 + buf * 16384;

        // ---- S = Q K^T ----
        float s[8][4];
        #pragma unroll
        for (int nt = 0; nt < 8; nt++)
            #pragma unroll
            for (int r = 0; r < 4; r++) s[nt][r] = 0.f;

        #pragma unroll
        for (int p = 0; p < 4; p++) {
            uint32_t af0[4], af1[4];
            ldsm4(af0, smQ + arow * 256 + SWZ64(arow, 4 * p + aqh) * 16);
            ldsm4(af1, smQ + arow * 256 + SWZ64(arow, 4 * p + 2 + aqh) * 16);
            #pragma unroll
            for (int nt = 0; nt < 8; nt++) {
                const int row = nt * 8 + b8;
                uint32_t bf[4];
                ldsm4(bf, smK + row * 256 + SWZ64(row, 4 * p + bqh) * 16);
                mma8(s[nt], af0, bf[0], bf[1]);
                mma8(s[nt], af1, bf[2], bf[3]);
            }
        }

        // ---- online softmax ----
        float mx0 = -1e30f, mx1 = -1e30f;
        #pragma unroll
        for (int nt = 0; nt < 8; nt++) {
            mx0 = fmaxf(mx0, fmaxf(s[nt][0], s[nt][1]));
            mx1 = fmaxf(mx1, fmaxf(s[nt][2], s[nt][3]));
        }
        mx0 = fmaxf(mx0, __shfl_xor_sync(0xffffffffu, mx0, 1));
        mx0 = fmaxf(mx0, __shfl_xor_sync(0xffffffffu, mx0, 2));
        mx1 = fmaxf(mx1, __shfl_xor_sync(0xffffffffu, mx1, 1));
        mx1 = fmaxf(mx1, __shfl_xor_sync(0xffffffffu, mx1, 2));

        const float mn0 = fmaxf(m0r, mx0 * SC + cb);
        const float mn1 = fmaxf(m1r, mx1 * SC + cb);
        const float rs0 = __expf(m0r - mn0);
        const float rs1 = __expf(m1r - mn1);
        m0r = mn0; m1r = mn1;

        const int row0 = wid * 16 + r4;
        const int row1 = row0 + 8;
        float sum0 = 0.f, sum1 = 0.f;
        #pragma unroll
        for (int nt = 0; nt < 8; nt++) {
            uint32_t p00 = tf32r(__expf(s[nt][0] * SC + cb - mn0));
            uint32_t p01 = tf32r(__expf(s[nt][1] * SC + cb - mn0));
            uint32_t p10 = tf32r(__expf(s[nt][2] * SC + cb - mn1));
            uint32_t p11 = tf32r(__expf(s[nt][3] * SC + cb - mn1));
            sum0 += __uint_as_float(p00) + __uint_as_float(p01);
            sum1 += __uint_as_float(p10) + __uint_as_float(p11);
            const int qd = nt * 2 + (q2 >> 2);
            const int i0 = row0 * 64 + SWZ64(row0, qd) * 4 + (q2 & 3);
            const int i1 = row1 * 64 + SWZ64(row1, qd) * 4 + (q2 & 3);
            *(uint2*)&asm_[32768 + i0] = make_uint2(p00, p01);
            *(uint2*)&asm_[32768 + i1] = make_uint2(p10, p11);
        }
        sum0 += __shfl_xor_sync(0xffffffffu, sum0, 1);
        sum0 += __shfl_xor_sync(0xffffffffu, sum0, 2);
        sum1 += __shfl_xor_sync(0xffffffffu, sum1, 1);
        sum1 += __shfl_xor_sync(0xffffffffu, sum1, 2);
        l0 = l0 * rs0 + sum0;
        l1 = l1 * rs1 + sum1;

        #pragma unroll
        for (int nt = 0; nt < 8; nt++) {
            o[nt][0] *= rs0; o[nt][1] *= rs0;
            o[nt][2] *= rs1; o[nt][3] *= rs1;
        }
        __syncwarp();   // P rows are warp-private

        // ---- O += P V ----
        #pragma unroll
        for (int p = 0; p < 4; p++) {
            uint32_t af0[4], af1[4];
            ldsm4(af0, smP + arow * 256 + SWZ64(arow, 4 * p + aqh) * 16);
            ldsm4(af1, smP + arow * 256 + SWZ64(arow, 4 * p + 2 + aqh) * 16);
            #pragma unroll
            for (int nt = 0; nt < 8; nt++) {
                const int row = nt * 8 + b8;   // d index
                uint32_t bf[4];
                ldsm4(bf, smV + row * 256 + SWZ64(row, 4 * p + bqh) * 16);
                mma8(o[nt], af0, bf[0], bf[1]);
                mma8(o[nt], af1, bf[2], bf[3]);
            }
        }

        if (kc < 31) {
            CP_WAIT(0);
            __syncthreads();
        }
    }

    // ---- normalize + write out (b, s, h*64+d) ----
    const float inv0 = 1.f / l0;
    const float inv1 = 1.f / l1;
    const int bb = bh >> 4, hh = bh & 15;
    const int gq0 = q0 + wid * 16 + r4;
    float* op0 = out + ((size_t)(bb * S_ + gq0)) * D_ + hh * DK;
    float* op1 = out + ((size_t)(bb * S_ + gq0 + 8)) * D_ + hh * DK;
    #pragma unroll
    for (int nt = 0; nt < 8; nt++) {
        const int d = nt * 8 + q2;
        float2 v0, v1;
        v0.x = o[nt][0] * inv0; v0.y = o[nt][1] * inv0;
        v1.x = o[nt][2] * inv1; v1.y = o[nt][3] * inv1;
        *(float2*)&op0[d] = v0;
        *(float2*)&op1[d] = v1;
    }
}

// ---------------------------------------------------------------------------
extern "C" void kernel_launch(void* const* d_in, const int* in_sizes, int n_in,
                              void* d_out, int out_size)
{
    const float* Xs  = (const float*)d_in[0];
    const float* Xt  = (const float*)d_in[1];
    const float* Wqs = (const float*)d_in[2];
    const float* bqs = (const float*)d_in[3];
    const float* Wqt = (const float*)d_in[4];
    const float* bqt = (const float*)d_in[5];
    const float* Wks = (const float*)d_in[6];
    const float* bks = (const float*)d_in[7];
    const float* Wkt = (const float*)d_in[8];
    const float* bkt = (const float*)d_in[9];
    const float* Wvs = (const float*)d_in[10];
    const float* bvs = (const float*)d_in[11];
    const float* Wvt = (const float*)d_in[12];
    const float* bvt = (const float*)d_in[13];
    const float* attn_bias = (const float*)d_in[14];
    float* out = (float*)d_out;

    cudaFuncSetAttribute(attn_mma,
        cudaFuncAttributeMaxDynamicSharedMemorySize, 196608);

    uint32_t* Xh; uint32_t* Xl; uint32_t* Wh; uint32_t* Wl;
    cudaGetSymbolAddress((void**)&Xh, g_Xh);
    cudaGetSymbolAddress((void**)&Xl, g_Xl);
    cudaGetSymbolAddress((void**)&Wh, g_Wh);
    cudaGetSymbolAddress((void**)&Wl, g_Wl);

    prep_split<<<dim3(64, 128), 256>>>(Xs, Xt, Xh, Xl);
    prep_split<<<dim3(8, 128), 256>>>(Wqs, Wqt, Wh, Wl);
    prep_split<<<dim3(8, 128), 256>>>(Wks, Wkt, Wh + 1048576, Wl + 1048576);
    prep_split<<<dim3(8, 128), 256>>>(Wvs, Wvt, Wh + 2097152, Wl + 2097152);

    dim3 gGrid(64, 24);
    qkv_gemm_v10<<<gGrid, 256>>>(bqs, bqt, bks, bkt, bvs, bvt);

    dim3 tGrid(32, B_ * H_);
    vtrans<<<tGrid, 256>>>();

    dim3 aGrid(8, B_ * H_);
    attn_mma<<<aGrid, 512, 196608>>>(attn_bias, out);
}

// round 14
// speedup vs baseline: 1.1080x; 1.0214x over previous
#include <cuda_runtime.h>
#include <cstdint>

#define B_  4
#define S_  2048
#define D_  1024
#define H_  16
#define DK  64

// Scratch: Q/K in (b, h, s, d); Vt in (b, h, d, s)
__device__ float g_Q [(size_t)B_*H_*S_*DK];
__device__ float g_K [(size_t)B_*H_*S_*DK];
__device__ float g_Vt[(size_t)B_*H_*S_*DK];

// Pre-split, pre-swizzled bf16 hi/lo tile images.
__device__ uint32_t g_Xh[(size_t)64*128*1024];
__device__ uint32_t g_Xl[(size_t)64*128*1024];
__device__ uint32_t g_Wh[(size_t)3*8*128*1024];
__device__ uint32_t g_Wl[(size_t)3*8*128*1024];

// ---------------------------------------------------------------------------
// Portable PTX helpers
// ---------------------------------------------------------------------------
__device__ __forceinline__ uint32_t smem_u32(const void* p) {
    uint32_t a;
    asm("{ .reg .u64 t; cvta.to.shared.u64 t, %1; cvt.u32.u64 %0, t; }"
        : "=r"(a) : "l"(p));
    return a;
}
__device__ __forceinline__ uint32_t tf32r(float f) {
    uint32_t u;
    asm("cvt.rna.tf32.f32 %0, %1;" : "=r"(u) : "f"(f));
    return u;
}
__device__ __forceinline__ void ldsm4(uint32_t r[4], uint32_t a) {
    asm volatile("ldmatrix.sync.aligned.m8n8.x4.shared.b16 {%0,%1,%2,%3}, [%4];"
        : "=r"(r[0]), "=r"(r[1]), "=r"(r[2]), "=r"(r[3]) : "r"(a));
}
// tf32 m16n8k8 (attention)
__device__ __forceinline__ void mma8(float* c, const uint32_t* a,
                                     uint32_t b0, uint32_t b1) {
    asm volatile("mma.sync.aligned.m16n8k8.row.col.f32.tf32.tf32.f32 "
        "{%0,%1,%2,%3}, {%4,%5,%6,%7}, {%8,%9}, {%0,%1,%2,%3};"
        : "+f"(c[0]), "+f"(c[1]), "+f"(c[2]), "+f"(c[3])
        : "r"(a[0]), "r"(a[1]), "r"(a[2]), "r"(a[3]), "r"(b0), "r"(b1));
}
// bf16 m16n8k16 (GEMM)
__device__ __forceinline__ void mma16(float* c, const uint32_t* a,
                                      uint32_t b0, uint32_t b1) {
    asm volatile("mma.sync.aligned.m16n8k16.row.col.f32.bf16.bf16.f32 "
        "{%0,%1,%2,%3}, {%4,%5,%6,%7}, {%8,%9}, {%0,%1,%2,%3};"
        : "+f"(c[0]), "+f"(c[1]), "+f"(c[2]), "+f"(c[3])
        : "r"(a[0]), "r"(a[1]), "r"(a[2]), "r"(a[3]), "r"(b0), "r"(b1));
}
__device__ __forceinline__ uint32_t packbf(float lo, float hi) {
    uint32_t r;
    asm("cvt.rn.bf16x2.f32 %0, %1, %2;" : "=r"(r) : "f"(hi), "f"(lo));
    return r;
}
__device__ __forceinline__ void split2(float f0, float f1,
                                       uint32_t& h, uint32_t& l) {
    h = packbf(f0, f1);
    float h0 = __uint_as_float(h << 16);
    float h1 = __uint_as_float(h & 0xffff0000u);
    l = packbf(f0 - h0, f1 - h1);
}
__device__ __forceinline__ void cp_async16(uint32_t s, const void* g) {
    asm volatile("cp.async.cg.shared.global [%0], [%1], 16;" :: "r"(s), "l"(g));
}
#define CP_COMMIT() asm volatile("cp.async.commit_group;" ::: "memory")
#define CP_WAIT(n)  asm volatile("cp.async.wait_group %0;" :: "n"(n) : "memory")

#define SWZ64(row, q) (((q) & 8) | ((((q) ^ ((row) & 7) ^ (((row) >> 3) & 7))) & 7))

// ---------------------------------------------------------------------------
// prep_split: fp32 (src_s | src_t along k) -> bf16 hi/lo tile images.
// ---------------------------------------------------------------------------
__global__ __launch_bounds__(256) void prep_split(
    const float* __restrict__ src_s, const float* __restrict__ src_t,
    uint32_t* __restrict__ dh, uint32_t* __restrict__ dl)
{
    const int rb = blockIdx.x, slab = blockIdx.y;   // slab 0..127
    const int t = threadIdx.x;
    const int row = t >> 1, half = t & 1;
    const float* src = (slab & 64) ? src_t : src_s;
    const float* p = src + (size_t)(rb * 128 + row) * 1024 + (slab & 63) * 16 + half * 8;
    float4 v0 = *(const float4*)p;
    float4 v1 = *(const float4*)(p + 4);
    uint32_t h[4], l[4];
    split2(v0.x, v0.y, h[0], l[0]); split2(v0.z, v0.w, h[1], l[1]);
    split2(v1.x, v1.y, h[2], l[2]); split2(v1.z, v1.w, h[3], l[3]);
    const size_t tile = ((size_t)rb * 128 + slab) * 1024;
    const int off = row * 8 + ((half ^ ((row >> 2) & 1)) * 4);   // u32 units
    *(uint4*)&dh[tile + off] = make_uint4(h[0], h[1], h[2], h[3]);
    *(uint4*)&dl[tile + off] = make_uint4(l[0], l[1], l[2], l[3]);
}

// ---------------------------------------------------------------------------
// QKV dual-linear GEMM, 3-term BF16, consuming pre-split tile images (v10).
// Block 128x128, BK=16, 8 warps (64x32 each), 2 CTAs/SM (48KB smem).
// V output (mi==2) is written TRANSPOSED into g_Vt (b,h,d,s) — vtrans fused.
// ---------------------------------------------------------------------------
__global__ __launch_bounds__(256, 2) void qkv_gemm_v13(
    const float* __restrict__ bqs, const float* __restrict__ bqt,
    const float* __restrict__ bks, const float* __restrict__ bkt,
    const float* __restrict__ bvs, const float* __restrict__ bvt)
{
    __shared__ uint32_t AH[3][1024], AL[3][1024], BH[3][1024], BL[3][1024];

    const int tid = threadIdx.x;
    const int lane = tid & 31;
    const int wid = tid >> 5;
    const int wr = wid >> 2;
    const int wc = wid & 3;

    const int bm = blockIdx.x;
    const int bn = blockIdx.y;
    const int mi = bn >> 3;
    const int n0 = (bn & 7) * 128;
    const int m0 = bm * 128;

    const float* bsp = (mi == 0) ? bqs : (mi == 1) ? bks : bvs;
    const float* btp = (mi == 0) ? bqt : (mi == 1) ? bkt : bvt;

    const uint32_t* Ah_g = g_Xh + (size_t)bm * 131072;
    const uint32_t* Al_g = g_Xl + (size_t)bm * 131072;
    const size_t wbase = ((size_t)mi * 8 + (bn & 7)) * 131072;
    const uint32_t* Bh_g = g_Wh + wbase;
    const uint32_t* Bl_g = g_Wl + wbase;

    float acc[4][4][4];
    #pragma unroll
    for (int mt = 0; mt < 4; mt++)
        #pragma unroll
        for (int nt = 0; nt < 4; nt++)
            #pragma unroll
            for (int r = 0; r < 4; r++) acc[mt][nt][r] = 0.f;

    const int t4 = tid * 4;

    const int l15 = lane & 15;
    const int qsw = (((lane >> 4) ^ ((l15 >> 2) & 1))) * 16;
    const int aRowOff = (wr * 64 + l15) * 32 + qsw;
    const int bRowOff = (wc * 32 + l15) * 32 + qsw;

    #pragma unroll
    for (int s = 0; s < 2; s++) {
        cp_async16(smem_u32(&AH[s][t4]), Ah_g + s * 1024 + t4);
        cp_async16(smem_u32(&AL[s][t4]), Al_g + s * 1024 + t4);
        cp_async16(smem_u32(&BH[s][t4]), Bh_g + s * 1024 + t4);
        cp_async16(smem_u32(&BL[s][t4]), Bl_g + s * 1024 + t4);
        CP_COMMIT();
    }

    int buf = 0;
    #pragma unroll 1
    for (int it = 0; it < 128; it++) {
        if (it < 127) { CP_WAIT(1); } else { CP_WAIT(0); }
        __syncthreads();

        if (it < 126) {
            const int st = (buf + 2 >= 3) ? (buf - 1) : (buf + 2);
            const int nt2 = (it + 2) * 1024 + t4;
            cp_async16(smem_u32(&AH[st][t4]), Ah_g + nt2);
            cp_async16(smem_u32(&AL[st][t4]), Al_g + nt2);
            cp_async16(smem_u32(&BH[st][t4]), Bh_g + nt2);
            cp_async16(smem_u32(&BL[st][t4]), Bl_g + nt2);
            CP_COMMIT();
        }

        const uint32_t aH = smem_u32(&AH[buf][0]);
        const uint32_t aL = smem_u32(&AL[buf][0]);
        const uint32_t bH = smem_u32(&BH[buf][0]);
        const uint32_t bL = smem_u32(&BL[buf][0]);

        uint32_t fAh[4][4], fAl[4][4];
        #pragma unroll
        for (int mt = 0; mt < 4; mt++) {
            ldsm4(fAh[mt], aH + aRowOff + mt * 512);
            ldsm4(fAl[mt], aL + aRowOff + mt * 512);
        }
        #pragma unroll
        for (int half = 0; half < 2; half++) {
            uint32_t fBh[4], fBl[4];
            ldsm4(fBh, bH + bRowOff + half * 512);
            ldsm4(fBl, bL + bRowOff + half * 512);
            #pragma unroll
            for (int n2 = 0; n2 < 2; n2++) {
                const int nt = half * 2 + n2;
                #pragma unroll
                for (int mt = 0; mt < 4; mt++) {
                    mma16(acc[mt][nt], fAh[mt], fBh[n2], fBh[n2 + 2]);
                    mma16(acc[mt][nt], fAl[mt], fBh[n2], fBh[n2 + 2]);
                    mma16(acc[mt][nt], fAh[mt], fBl[n2], fBl[n2 + 2]);
                }
            }
        }
        buf = (buf == 2) ? 0 : (buf + 1);
    }

    // Epilogue: add biases, round to tf32. Q/K -> (b,h,s,d); V -> g_Vt (b,h,d,s).
    const int r4 = lane >> 2;
    const int q2 = (lane & 3) * 2;
    #pragma unroll
    for (int mt = 0; mt < 4; mt++) {
        const int t = m0 + wr * 64 + mt * 16 + r4;
        #pragma unroll
        for (int nt = 0; nt < 4; nt++) {
            const int c0 = n0 + wc * 32 + nt * 8 + q2;
            const float bx = bsp[c0] + btp[c0];
            const float by = bsp[c0 + 1] + btp[c0 + 1];
            const int h = c0 >> 6, d = c0 & 63;
            #pragma unroll
            for (int half = 0; half < 2; half++) {
                const int tt = t + half * 8;
                const int bb = tt >> 11;
                const int ss = tt & 2047;
                float vx = __uint_as_float(tf32r(acc[mt][nt][half * 2 + 0] + bx));
                float vy = __uint_as_float(tf32r(acc[mt][nt][half * 2 + 1] + by));
                if (mi == 2) {
                    float* vt = g_Vt + (((size_t)(bb * H_ + h)) * DK + d) * S_ + ss;
                    vt[0]  = vx;
                    vt[S_] = vy;
                } else {
                    float* Out = (mi == 0) ? g_Q : g_K;
                    *(float2*)&Out[(((size_t)(bb * H_ + h)) * S_ + ss) * DK + d] =
                        make_float2(vx, vy);
                }
            }
        }
    }
}

// ---------------------------------------------------------------------------
// Flash attention (tf32 mma.sync). BQ=128 (8 warps x 16 rows), BK=64.
// Q fragments hoisted to registers; ONE __syncthreads per chunk. (R10 exact)
// smem (128KB dynamic, bytes): Q[0,32K), K 2x16K at 32K, Vt 2x16K at 64K,
// P[96K,128K).
// ---------------------------------------------------------------------------
__global__ __launch_bounds__(256) void attn_mma(
    const float* __restrict__ bias_p, float* __restrict__ out)
{
    extern __shared__ uint32_t asm_[];
    const uint32_t base = smem_u32(asm_);
    const uint32_t smQ = base;
    const uint32_t smP = base + 98304;

    const int tid = threadIdx.x;
    const int lane = tid & 31;
    const int wid = tid >> 5;

    const int qt = blockIdx.x;
    const int bh = blockIdx.y;
    const int q0 = qt * 128;
    const float* Q  = g_Q  + (size_t)bh * S_ * DK;
    const float* K  = g_K  + (size_t)bh * S_ * DK;
    const float* Vt = g_Vt + (size_t)bh * S_ * DK;   // (d, s)
    const float cb = bias_p[0];
    const float SC = 0.125f;

    // ---- prologue: Q + chunk0 via cp.async (one group) ----
    #pragma unroll
    for (int i = 0; i < 8; i++) {
        int idx = tid + 256 * i;
        int row = idx >> 4, q = idx & 15;
        cp_async16(smQ + (row * 64 + SWZ64(row, q) * 4) * 4,
                   Q + (size_t)(q0 + row) * DK + q * 4);
    }
    #pragma unroll
    for (int i = 0; i < 4; i++) {
        int idx = tid + 256 * i;
        int row = idx >> 4, q = idx & 15;
        cp_async16(base + 32768 + (row * 64 + SWZ64(row, q) * 4) * 4,
                   K + (size_t)row * DK + q * 4);
        cp_async16(base + 65536 + (row * 64 + SWZ64(row, q) * 4) * 4,
                   Vt + (size_t)row * S_ + q * 4);
    }
    CP_COMMIT();

    const int arow = wid * 16 + (lane & 15);
    const int aqh = lane >> 4;
    const int b8 = lane & 7;
    const int bqh = lane >> 3;
    const int r4 = lane >> 2;
    const int q2 = (lane & 3) * 2;

    CP_WAIT(0);
    __syncthreads();

    // ---- hoist Q fragments (loop-invariant) ----
    uint32_t fQ0[4][4], fQ1[4][4];
    #pragma unroll
    for (int p = 0; p < 4; p++) {
        ldsm4(fQ0[p], smQ + arow * 256 + SWZ64(arow, 4 * p + aqh) * 16);
        ldsm4(fQ1[p], smQ + arow * 256 + SWZ64(arow, 4 * p + 2 + aqh) * 16);
    }

    float o[8][4];
    #pragma unroll
    for (int nt = 0; nt < 8; nt++)
        #pragma unroll
        for (int r = 0; r < 4; r++) o[nt][r] = 0.f;
    float m0r = -1e30f, m1r = -1e30f, l0 = 0.f, l1 = 0.f;

    #pragma unroll 1
    for (int kc = 0; kc < 32; kc++) {
        const int buf = kc & 1;
        if (kc < 31) {
            const int nb = (kc + 1) & 1;
            const int k0 = (kc + 1) * 64;
            #pragma unroll
            for (int i = 0; i < 4; i++) {
                int idx = tid + 256 * i;
                int row = idx >> 4, q = idx & 15;
                cp_async16(base + 32768 + nb * 16384 + (row * 64 + SWZ64(row, q) * 4) * 4,
                           K + (size_t)(k0 + row) * DK + q * 4);
                cp_async16(base + 65536 + nb * 16384 + (row * 64 + SWZ64(row, q) * 4) * 4,
                           Vt + (size_t)row * S_ + k0 + q * 4);
            }
            CP_COMMIT();
        }

        const uint32_t smK = base + 32768 + buf * 16384;
        const uint32_t smV = base + 65536 + buf * 16384;

        // ---- S = Q K^T ----
        float s[8][4];
        #pragma unroll
        for (int nt = 0; nt < 8; nt++)
            #pragma unroll
            for (int r = 0; r < 4; r++) s[nt][r] = 0.f;

        #pragma unroll
        for (int p = 0; p < 4; p++) {
            #pragma unroll
            for (int nt = 0; nt < 8; nt++) {
                const int row = nt * 8 + b8;
                uint32_t bf[4];
                ldsm4(bf, smK + row * 256 + SWZ64(row, 4 * p + bqh) * 16);
                mma8(s[nt], fQ0[p], bf[0], bf[1]);
                mma8(s[nt], fQ1[p], bf[2], bf[3]);
            }
        }

        // ---- online softmax ----
        float mx0 = -1e30f, mx1 = -1e30f;
        #pragma unroll
        for (int nt = 0; nt < 8; nt++) {
            mx0 = fmaxf(mx0, fmaxf(s[nt][0], s[nt][1]));
            mx1 = fmaxf(mx1, fmaxf(s[nt][2], s[nt][3]));
        }
        mx0 = fmaxf(mx0, __shfl_xor_sync(0xffffffffu, mx0, 1));
        mx0 = fmaxf(mx0, __shfl_xor_sync(0xffffffffu, mx0, 2));
        mx1 = fmaxf(mx1, __shfl_xor_sync(0xffffffffu, mx1, 1));
        mx1 = fmaxf(mx1, __shfl_xor_sync(0xffffffffu, mx1, 2));

        const float mn0 = fmaxf(m0r, mx0 * SC + cb);
        const float mn1 = fmaxf(m1r, mx1 * SC + cb);
        const float rs0 = __expf(m0r - mn0);
        const float rs1 = __expf(m1r - mn1);
        m0r = mn0; m1r = mn1;

        const int row0 = wid * 16 + r4;
        const int row1 = row0 + 8;
        float sum0 = 0.f, sum1 = 0.f;
        #pragma unroll
        for (int nt = 0; nt < 8; nt++) {
            uint32_t p00 = tf32r(__expf(s[nt][0] * SC + cb - mn0));
            uint32_t p01 = tf32r(__expf(s[nt][1] * SC + cb - mn0));
            uint32_t p10 = tf32r(__expf(s[nt][2] * SC + cb - mn1));
            uint32_t p11 = tf32r(__expf(s[nt][3] * SC + cb - mn1));
            sum0 += __uint_as_float(p00) + __uint_as_float(p01);
            sum1 += __uint_as_float(p10) + __uint_as_float(p11);
            const int qd = nt * 2 + (q2 >> 2);
            const int i0 = row0 * 64 + SWZ64(row0, qd) * 4 + (q2 & 3);
            const int i1 = row1 * 64 + SWZ64(row1, qd) * 4 + (q2 & 3);
            *(uint2*)&asm_[24576 + i0] = make_uint2(p00, p01);
            *(uint2*)&asm_[24576 + i1] = make_uint2(p10, p11);
        }
        sum0 += __shfl_xor_sync(0xffffffffu, sum0, 1);
        sum0 += __shfl_xor_sync(0xffffffffu, sum0, 2);
        sum1 += __shfl_xor_sync(0xffffffffu, sum1, 1);
        sum1 += __shfl_xor_sync(0xffffffffu, sum1, 2);
        l0 = l0 * rs0 + sum0;
        l1 = l1 * rs1 + sum1;

        #pragma unroll
        for (int nt = 0; nt < 8; nt++) {
            o[nt][0] *= rs0; o[nt][1] *= rs0;
            o[nt][2] *= rs1; o[nt][3] *= rs1;
        }
        __syncwarp();   // P rows are warp-private

        // ---- O += P V ----
        #pragma unroll
        for (int p = 0; p < 4; p++) {
            uint32_t af0[4], af1[4];
            ldsm4(af0, smP + arow * 256 + SWZ64(arow, 4 * p + aqh) * 16);
            ldsm4(af1, smP + arow * 256 + SWZ64(arow, 4 * p + 2 + aqh) * 16);
            #pragma unroll
            for (int nt = 0; nt < 8; nt++) {
                const int row = nt * 8 + b8;   // d index
                uint32_t bf[4];
                ldsm4(bf, smV + row * 256 + SWZ64(row, 4 * p + bqh) * 16);
                mma8(o[nt], af0, bf[0], bf[1]);
                mma8(o[nt], af1, bf[2], bf[3]);
            }
        }

        if (kc < 31) {
            CP_WAIT(0);
            __syncthreads();
        }
    }

    // ---- normalize + write out (b, s, h*64+d) ----
    const float inv0 = 1.f / l0;
    const float inv1 = 1.f / l1;
    const int bb = bh >> 4, hh = bh & 15;
    const int gq0 = q0 + wid * 16 + r4;
    float* op0 = out + ((size_t)(bb * S_ + gq0)) * D_ + hh * DK;
    float* op1 = out + ((size_t)(bb * S_ + gq0 + 8)) * D_ + hh * DK;
    #pragma unroll
    for (int nt = 0; nt < 8; nt++) {
        const int d = nt * 8 + q2;
        float2 v0, v1;
        v0.x = o[nt][0] * inv0; v0.y = o[nt][1] * inv0;
        v1.x = o[nt][2] * inv1; v1.y = o[nt][3] * inv1;
        *(float2*)&op0[d] = v0;
        *(float2*)&op1[d] = v1;
    }
}

// ---------------------------------------------------------------------------
extern "C" void kernel_launch(void* const* d_in, const int* in_sizes, int n_in,
                              void* d_out, int out_size)
{
    const float* Xs  = (const float*)d_in[0];
    const float* Xt  = (const float*)d_in[1];
    const float* Wqs = (const float*)d_in[2];
    const float* bqs = (const float*)d_in[3];
    const float* Wqt = (const float*)d_in[4];
    const float* bqt = (const float*)d_in[5];
    const float* Wks = (const float*)d_in[6];
    const float* bks = (const float*)d_in[7];
    const float* Wkt = (const float*)d_in[8];
    const float* bkt = (const float*)d_in[9];
    const float* Wvs = (const float*)d_in[10];
    const float* bvs = (const float*)d_in[11];
    const float* Wvt = (const float*)d_in[12];
    const float* bvt = (const float*)d_in[13];
    const float* attn_bias = (const float*)d_in[14];
    float* out = (float*)d_out;

    cudaFuncSetAttribute(attn_mma,
        cudaFuncAttributeMaxDynamicSharedMemorySize, 131072);

    uint32_t* Xh; uint32_t* Xl; uint32_t* Wh; uint32_t* Wl;
    cudaGetSymbolAddress((void**)&Xh, g_Xh);
    cudaGetSymbolAddress((void**)&Xl, g_Xl);
    cudaGetSymbolAddress((void**)&Wh, g_Wh);
    cudaGetSymbolAddress((void**)&Wl, g_Wl);

    prep_split<<<dim3(64, 128), 256>>>(Xs, Xt, Xh, Xl);
    prep_split<<<dim3(8, 128), 256>>>(Wqs, Wqt, Wh, Wl);
    prep_split<<<dim3(8, 128), 256>>>(Wks, Wkt, Wh + 1048576, Wl + 1048576);
    prep_split<<<dim3(8, 128), 256>>>(Wvs, Wvt, Wh + 2097152, Wl + 2097152);

    dim3 gGrid(64, 24);
    qkv_gemm_v13<<<gGrid, 256>>>(bqs, bqt, bks, bkt, bvs, bvt);

    dim3 aGrid(16, B_ * H_);
    attn_mma<<<aGrid, 256, 131072>>>(attn_bias, out);
}

// round 15
// speedup vs baseline: 1.1450x; 1.0334x over previous
#include <cuda_runtime.h>
#include <cstdint>

#define B_  4
#define S_  2048
#define D_  1024
#define H_  16
#define DK  64

// Scratch: Q/K in (b, h, s, d); Vt in (b, h, d, s)
__device__ float g_Q [(size_t)B_*H_*S_*DK];
__device__ float g_K [(size_t)B_*H_*S_*DK];
__device__ float g_Vt[(size_t)B_*H_*S_*DK];

// Pre-split, pre-swizzled bf16 hi/lo tile images.
__device__ uint32_t g_Xh[(size_t)64*128*1024];
__device__ uint32_t g_Xl[(size_t)64*128*1024];
__device__ uint32_t g_Wh[(size_t)3*8*128*1024];
__device__ uint32_t g_Wl[(size_t)3*8*128*1024];

// ---------------------------------------------------------------------------
// Portable PTX helpers
// ---------------------------------------------------------------------------
__device__ __forceinline__ uint32_t smem_u32(const void* p) {
    uint32_t a;
    asm("{ .reg .u64 t; cvta.to.shared.u64 t, %1; cvt.u32.u64 %0, t; }"
        : "=r"(a) : "l"(p));
    return a;
}
__device__ __forceinline__ uint32_t tf32r(float f) {
    uint32_t u;
    asm("cvt.rna.tf32.f32 %0, %1;" : "=r"(u) : "f"(f));
    return u;
}
__device__ __forceinline__ void ldsm4(uint32_t r[4], uint32_t a) {
    asm volatile("ldmatrix.sync.aligned.m8n8.x4.shared.b16 {%0,%1,%2,%3}, [%4];"
        : "=r"(r[0]), "=r"(r[1]), "=r"(r[2]), "=r"(r[3]) : "r"(a));
}
// tf32 m16n8k8 (attention)
__device__ __forceinline__ void mma8(float* c, const uint32_t* a,
                                     uint32_t b0, uint32_t b1) {
    asm volatile("mma.sync.aligned.m16n8k8.row.col.f32.tf32.tf32.f32 "
        "{%0,%1,%2,%3}, {%4,%5,%6,%7}, {%8,%9}, {%0,%1,%2,%3};"
        : "+f"(c[0]), "+f"(c[1]), "+f"(c[2]), "+f"(c[3])
        : "r"(a[0]), "r"(a[1]), "r"(a[2]), "r"(a[3]), "r"(b0), "r"(b1));
}
// bf16 m16n8k16 (GEMM)
__device__ __forceinline__ void mma16(float* c, const uint32_t* a,
                                      uint32_t b0, uint32_t b1) {
    asm volatile("mma.sync.aligned.m16n8k16.row.col.f32.bf16.bf16.f32 "
        "{%0,%1,%2,%3}, {%4,%5,%6,%7}, {%8,%9}, {%0,%1,%2,%3};"
        : "+f"(c[0]), "+f"(c[1]), "+f"(c[2]), "+f"(c[3])
        : "r"(a[0]), "r"(a[1]), "r"(a[2]), "r"(a[3]), "r"(b0), "r"(b1));
}
__device__ __forceinline__ uint32_t packbf(float lo, float hi) {
    uint32_t r;
    asm("cvt.rn.bf16x2.f32 %0, %1, %2;" : "=r"(r) : "f"(hi), "f"(lo));
    return r;
}
__device__ __forceinline__ void split2(float f0, float f1,
                                       uint32_t& h, uint32_t& l) {
    h = packbf(f0, f1);
    float h0 = __uint_as_float(h << 16);
    float h1 = __uint_as_float(h & 0xffff0000u);
    l = packbf(f0 - h0, f1 - h1);
}
__device__ __forceinline__ void cp_async16(uint32_t s, const void* g) {
    asm volatile("cp.async.cg.shared.global [%0], [%1], 16;" :: "r"(s), "l"(g));
}
#define CP_COMMIT() asm volatile("cp.async.commit_group;" ::: "memory")
#define CP_WAIT(n)  asm volatile("cp.async.wait_group %0;" :: "n"(n) : "memory")

#define SWZ64(row, q) (((q) & 8) | ((((q) ^ ((row) & 7) ^ (((row) >> 3) & 7))) & 7))

// ---------------------------------------------------------------------------
// prep_split: fp32 (src_s | src_t along k) -> bf16 hi/lo tile images.
// ---------------------------------------------------------------------------
__global__ __launch_bounds__(256) void prep_split(
    const float* __restrict__ src_s, const float* __restrict__ src_t,
    uint32_t* __restrict__ dh, uint32_t* __restrict__ dl)
{
    const int rb = blockIdx.x, slab = blockIdx.y;   // slab 0..127
    const int t = threadIdx.x;
    const int row = t >> 1, half = t & 1;
    const float* src = (slab & 64) ? src_t : src_s;
    const float* p = src + (size_t)(rb * 128 + row) * 1024 + (slab & 63) * 16 + half * 8;
    float4 v0 = *(const float4*)p;
    float4 v1 = *(const float4*)(p + 4);
    uint32_t h[4], l[4];
    split2(v0.x, v0.y, h[0], l[0]); split2(v0.z, v0.w, h[1], l[1]);
    split2(v1.x, v1.y, h[2], l[2]); split2(v1.z, v1.w, h[3], l[3]);
    const size_t tile = ((size_t)rb * 128 + slab) * 1024;
    const int off = row * 8 + ((half ^ ((row >> 2) & 1)) * 4);   // u32 units
    *(uint4*)&dh[tile + off] = make_uint4(h[0], h[1], h[2], h[3]);
    *(uint4*)&dl[tile + off] = make_uint4(l[0], l[1], l[2], l[3]);
}

// ---------------------------------------------------------------------------
// QKV dual-linear GEMM, 3-term BF16, consuming pre-split tile images.
// Block 128x128, BK=16, 8 warps (64x32 each), 2 CTAs/SM (48KB smem).
// V output (mi==2) written TRANSPOSED into g_Vt (b,h,d,s) — vtrans fused.
// ---------------------------------------------------------------------------
__global__ __launch_bounds__(256, 2) void qkv_gemm_v13(
    const float* __restrict__ bqs, const float* __restrict__ bqt,
    const float* __restrict__ bks, const float* __restrict__ bkt,
    const float* __restrict__ bvs, const float* __restrict__ bvt)
{
    __shared__ uint32_t AH[3][1024], AL[3][1024], BH[3][1024], BL[3][1024];

    const int tid = threadIdx.x;
    const int lane = tid & 31;
    const int wid = tid >> 5;
    const int wr = wid >> 2;
    const int wc = wid & 3;

    const int bm = blockIdx.x;
    const int bn = blockIdx.y;
    const int mi = bn >> 3;
    const int n0 = (bn & 7) * 128;
    const int m0 = bm * 128;

    const float* bsp = (mi == 0) ? bqs : (mi == 1) ? bks : bvs;
    const float* btp = (mi == 0) ? bqt : (mi == 1) ? bkt : bvt;

    const uint32_t* Ah_g = g_Xh + (size_t)bm * 131072;
    const uint32_t* Al_g = g_Xl + (size_t)bm * 131072;
    const size_t wbase = ((size_t)mi * 8 + (bn & 7)) * 131072;
    const uint32_t* Bh_g = g_Wh + wbase;
    const uint32_t* Bl_g = g_Wl + wbase;

    float acc[4][4][4];
    #pragma unroll
    for (int mt = 0; mt < 4; mt++)
        #pragma unroll
        for (int nt = 0; nt < 4; nt++)
            #pragma unroll
            for (int r = 0; r < 4; r++) acc[mt][nt][r] = 0.f;

    const int t4 = tid * 4;

    const int l15 = lane & 15;
    const int qsw = (((lane >> 4) ^ ((l15 >> 2) & 1))) * 16;
    const int aRowOff = (wr * 64 + l15) * 32 + qsw;
    const int bRowOff = (wc * 32 + l15) * 32 + qsw;

    #pragma unroll
    for (int s = 0; s < 2; s++) {
        cp_async16(smem_u32(&AH[s][t4]), Ah_g + s * 1024 + t4);
        cp_async16(smem_u32(&AL[s][t4]), Al_g + s * 1024 + t4);
        cp_async16(smem_u32(&BH[s][t4]), Bh_g + s * 1024 + t4);
        cp_async16(smem_u32(&BL[s][t4]), Bl_g + s * 1024 + t4);
        CP_COMMIT();
    }

    int buf = 0;
    #pragma unroll 1
    for (int it = 0; it < 128; it++) {
        if (it < 127) { CP_WAIT(1); } else { CP_WAIT(0); }
        __syncthreads();

        if (it < 126) {
            const int st = (buf + 2 >= 3) ? (buf - 1) : (buf + 2);
            const int nt2 = (it + 2) * 1024 + t4;
            cp_async16(smem_u32(&AH[st][t4]), Ah_g + nt2);
            cp_async16(smem_u32(&AL[st][t4]), Al_g + nt2);
            cp_async16(smem_u32(&BH[st][t4]), Bh_g + nt2);
            cp_async16(smem_u32(&BL[st][t4]), Bl_g + nt2);
            CP_COMMIT();
        }

        const uint32_t aH = smem_u32(&AH[buf][0]);
        const uint32_t aL = smem_u32(&AL[buf][0]);
        const uint32_t bH = smem_u32(&BH[buf][0]);
        const uint32_t bL = smem_u32(&BL[buf][0]);

        uint32_t fAh[4][4], fAl[4][4];
        #pragma unroll
        for (int mt = 0; mt < 4; mt++) {
            ldsm4(fAh[mt], aH + aRowOff + mt * 512);
            ldsm4(fAl[mt], aL + aRowOff + mt * 512);
        }
        #pragma unroll
        for (int half = 0; half < 2; half++) {
            uint32_t fBh[4], fBl[4];
            ldsm4(fBh, bH + bRowOff + half * 512);
            ldsm4(fBl, bL + bRowOff + half * 512);
            #pragma unroll
            for (int n2 = 0; n2 < 2; n2++) {
                const int nt = half * 2 + n2;
                #pragma unroll
                for (int mt = 0; mt < 4; mt++) {
                    mma16(acc[mt][nt], fAh[mt], fBh[n2], fBh[n2 + 2]);
                    mma16(acc[mt][nt], fAl[mt], fBh[n2], fBh[n2 + 2]);
                    mma16(acc[mt][nt], fAh[mt], fBl[n2], fBl[n2 + 2]);
                }
            }
        }
        buf = (buf == 2) ? 0 : (buf + 1);
    }

    // Epilogue: add biases, round to tf32. Q/K -> (b,h,s,d); V -> g_Vt (b,h,d,s).
    const int r4 = lane >> 2;
    const int q2 = (lane & 3) * 2;
    #pragma unroll
    for (int mt = 0; mt < 4; mt++) {
        const int t = m0 + wr * 64 + mt * 16 + r4;
        #pragma unroll
        for (int nt = 0; nt < 4; nt++) {
            const int c0 = n0 + wc * 32 + nt * 8 + q2;
            const float bx = bsp[c0] + btp[c0];
            const float by = bsp[c0 + 1] + btp[c0 + 1];
            const int h = c0 >> 6, d = c0 & 63;
            #pragma unroll
            for (int half = 0; half < 2; half++) {
                const int tt = t + half * 8;
                const int bb = tt >> 11;
                const int ss = tt & 2047;
                float vx = __uint_as_float(tf32r(acc[mt][nt][half * 2 + 0] + bx));
                float vy = __uint_as_float(tf32r(acc[mt][nt][half * 2 + 1] + by));
                if (mi == 2) {
                    float* vt = g_Vt + (((size_t)(bb * H_ + h)) * DK + d) * S_ + ss;
                    vt[0]  = vx;
                    vt[S_] = vy;
                } else {
                    float* Out = (mi == 0) ? g_Q : g_K;
                    *(float2*)&Out[(((size_t)(bb * H_ + h)) * S_ + ss) * DK + d] =
                        make_float2(vx, vy);
                }
            }
        }
    }
}

// ---------------------------------------------------------------------------
// Flash attention (tf32 mma.sync). BQ=128 (8 warps x 16 rows), BK=64.
// Q fragments hoisted; P OVERLAYS the dead Q smem buffer -> 96KB smem
// -> 2 CTAs/SM. Per-warp strips are private for Q-hoist and P (no hazard).
// smem (96KB dynamic, bytes): Q/P [0,32K), K 2x16K at 32K, Vt 2x16K at 64K.
// ---------------------------------------------------------------------------
__global__ __launch_bounds__(256, 2) void attn_mma(
    const float* __restrict__ bias_p, float* __restrict__ out)
{
    extern __shared__ uint32_t asm_[];
    const uint32_t base = smem_u32(asm_);
    const uint32_t smQ = base;
    const uint32_t smP = base;          // overlay: Q dead after hoist

    const int tid = threadIdx.x;
    const int lane = tid & 31;
    const int wid = tid >> 5;

    const int qt = blockIdx.x;
    const int bh = blockIdx.y;
    const int q0 = qt * 128;
    const float* Q  = g_Q  + (size_t)bh * S_ * DK;
    const float* K  = g_K  + (size_t)bh * S_ * DK;
    const float* Vt = g_Vt + (size_t)bh * S_ * DK;   // (d, s)
    const float cb = bias_p[0];
    const float SC = 0.125f;

    // ---- prologue: Q + chunk0 via cp.async (one group) ----
    #pragma unroll
    for (int i = 0; i < 8; i++) {
        int idx = tid + 256 * i;
        int row = idx >> 4, q = idx & 15;
        cp_async16(smQ + (row * 64 + SWZ64(row, q) * 4) * 4,
                   Q + (size_t)(q0 + row) * DK + q * 4);
    }
    #pragma unroll
    for (int i = 0; i < 4; i++) {
        int idx = tid + 256 * i;
        int row = idx >> 4, q = idx & 15;
        cp_async16(base + 32768 + (row * 64 + SWZ64(row, q) * 4) * 4,
                   K + (size_t)row * DK + q * 4);
        cp_async16(base + 65536 + (row * 64 + SWZ64(row, q) * 4) * 4,
                   Vt + (size_t)row * S_ + q * 4);
    }
    CP_COMMIT();

    const int arow = wid * 16 + (lane & 15);
    const int aqh = lane >> 4;
    const int b8 = lane & 7;
    const int bqh = lane >> 3;
    const int r4 = lane >> 2;
    const int q2 = (lane & 3) * 2;

    CP_WAIT(0);
    __syncthreads();

    // ---- hoist Q fragments (loop-invariant; frees the Q buffer for P) ----
    uint32_t fQ0[4][4], fQ1[4][4];
    #pragma unroll
    for (int p = 0; p < 4; p++) {
        ldsm4(fQ0[p], smQ + arow * 256 + SWZ64(arow, 4 * p + aqh) * 16);
        ldsm4(fQ1[p], smQ + arow * 256 + SWZ64(arow, 4 * p + 2 + aqh) * 16);
    }

    float o[8][4];
    #pragma unroll
    for (int nt = 0; nt < 8; nt++)
        #pragma unroll
        for (int r = 0; r < 4; r++) o[nt][r] = 0.f;
    float m0r = -1e30f, m1r = -1e30f, l0 = 0.f, l1 = 0.f;

    #pragma unroll 1
    for (int kc = 0; kc < 32; kc++) {
        const int buf = kc & 1;
        if (kc < 31) {
            const int nb = (kc + 1) & 1;
            const int k0 = (kc + 1) * 64;
            #pragma unroll
            for (int i = 0; i < 4; i++) {
                int idx = tid + 256 * i;
                int row = idx >> 4, q = idx & 15;
                cp_async16(base + 32768 + nb * 16384 + (row * 64 + SWZ64(row, q) * 4) * 4,
                           K + (size_t)(k0 + row) * DK + q * 4);
                cp_async16(base + 65536 + nb * 16384 + (row * 64 + SWZ64(row, q) * 4) * 4,
                           Vt + (size_t)row * S_ + k0 + q * 4);
            }
            CP_COMMIT();
        }

        const uint32_t smK = base + 32768 + buf * 16384;
        const uint32_t smV = base + 65536 + buf * 16384;

        // ---- S = Q K^T ----
        float s[8][4];
        #pragma unroll
        for (int nt = 0; nt < 8; nt++)
            #pragma unroll
            for (int r = 0; r < 4; r++) s[nt][r] = 0.f;

        #pragma unroll
        for (int p = 0; p < 4; p++) {
            #pragma unroll
            for (int nt = 0; nt < 8; nt++) {
                const int row = nt * 8 + b8;
                uint32_t bf[4];
                ldsm4(bf, smK + row * 256 + SWZ64(row, 4 * p + bqh) * 16);
                mma8(s[nt], fQ0[p], bf[0], bf[1]);
                mma8(s[nt], fQ1[p], bf[2], bf[3]);
            }
        }

        // ---- online softmax ----
        float mx0 = -1e30f, mx1 = -1e30f;
        #pragma unroll
        for (int nt = 0; nt < 8; nt++) {
            mx0 = fmaxf(mx0, fmaxf(s[nt][0], s[nt][1]));
            mx1 = fmaxf(mx1, fmaxf(s[nt][2], s[nt][3]));
        }
        mx0 = fmaxf(mx0, __shfl_xor_sync(0xffffffffu, mx0, 1));
        mx0 = fmaxf(mx0, __shfl_xor_sync(0xffffffffu, mx0, 2));
        mx1 = fmaxf(mx1, __shfl_xor_sync(0xffffffffu, mx1, 1));
        mx1 = fmaxf(mx1, __shfl_xor_sync(0xffffffffu, mx1, 2));

        const float mn0 = fmaxf(m0r, mx0 * SC + cb);
        const float mn1 = fmaxf(m1r, mx1 * SC + cb);
        const float rs0 = __expf(m0r - mn0);
        const float rs1 = __expf(m1r - mn1);
        m0r = mn0; m1r = mn1;

        const int row0 = wid * 16 + r4;
        const int row1 = row0 + 8;
        float sum0 = 0.f, sum1 = 0.f;
        #pragma unroll
        for (int nt = 0; nt < 8; nt++) {
            uint32_t p00 = tf32r(__expf(s[nt][0] * SC + cb - mn0));
            uint32_t p01 = tf32r(__expf(s[nt][1] * SC + cb - mn0));
            uint32_t p10 = tf32r(__expf(s[nt][2] * SC + cb - mn1));
            uint32_t p11 = tf32r(__expf(s[nt][3] * SC + cb - mn1));
            sum0 += __uint_as_float(p00) + __uint_as_float(p01);
            sum1 += __uint_as_float(p10) + __uint_as_float(p11);
            const int qd = nt * 2 + (q2 >> 2);
            const int i0 = row0 * 64 + SWZ64(row0, qd) * 4 + (q2 & 3);
            const int i1 = row1 * 64 + SWZ64(row1, qd) * 4 + (q2 & 3);
            *(uint2*)&asm_[i0] = make_uint2(p00, p01);
            *(uint2*)&asm_[i1] = make_uint2(p10, p11);
        }
        sum0 += __shfl_xor_sync(0xffffffffu, sum0, 1);
        sum0 += __shfl_xor_sync(0xffffffffu, sum0, 2);
        sum1 += __shfl_xor_sync(0xffffffffu, sum1, 1);
        sum1 += __shfl_xor_sync(0xffffffffu, sum1, 2);
        l0 = l0 * rs0 + sum0;
        l1 = l1 * rs1 + sum1;

        #pragma unroll
        for (int nt = 0; nt < 8; nt++) {
            o[nt][0] *= rs0; o[nt][1] *= rs0;
            o[nt][2] *= rs1; o[nt][3] *= rs1;
        }
        __syncwarp();   // P rows are warp-private

        // ---- O += P V ----
        #pragma unroll
        for (int p = 0; p < 4; p++) {
            uint32_t af0[4], af1[4];
            ldsm4(af0, smP + arow * 256 + SWZ64(arow, 4 * p + aqh) * 16);
            ldsm4(af1, smP + arow * 256 + SWZ64(arow, 4 * p + 2 + aqh) * 16);
            #pragma unroll
            for (int nt = 0; nt < 8; nt++) {
                const int row = nt * 8 + b8;   // d index
                uint32_t bf[4];
                ldsm4(bf, smV + row * 256 + SWZ64(row, 4 * p + bqh) * 16);
                mma8(o[nt], af0, bf[0], bf[1]);
                mma8(o[nt], af1, bf[2], bf[3]);
            }
        }

        if (kc < 31) {
            CP_WAIT(0);
            __syncthreads();
        }
    }

    // ---- normalize + write out (b, s, h*64+d) ----
    const float inv0 = 1.f / l0;
    const float inv1 = 1.f / l1;
    const int bb = bh >> 4, hh = bh & 15;
    const int gq0 = q0 + wid * 16 + r4;
    float* op0 = out + ((size_t)(bb * S_ + gq0)) * D_ + hh * DK;
    float* op1 = out + ((size_t)(bb * S_ + gq0 + 8)) * D_ + hh * DK;
    #pragma unroll
    for (int nt = 0; nt < 8; nt++) {
        const int d = nt * 8 + q2;
        float2 v0, v1;
        v0.x = o[nt][0] * inv0; v0.y = o[nt][1] * inv0;
        v1.x = o[nt][2] * inv1; v1.y = o[nt][3] * inv1;
        *(float2*)&op0[d] = v0;
        *(float2*)&op1[d] = v1;
    }
}

// ---------------------------------------------------------------------------
extern "C" void kernel_launch(void* const* d_in, const int* in_sizes, int n_in,
                              void* d_out, int out_size)
{
    const float* Xs  = (const float*)d_in[0];
    const float* Xt  = (const float*)d_in[1];
    const float* Wqs = (const float*)d_in[2];
    const float* bqs = (const float*)d_in[3];
    const float* Wqt = (const float*)d_in[4];
    const float* bqt = (const float*)d_in[5];
    const float* Wks = (const float*)d_in[6];
    const float* bks = (const float*)d_in[7];
    const float* Wkt = (const float*)d_in[8];
    const float* bkt = (const float*)d_in[9];
    const float* Wvs = (const float*)d_in[10];
    const float* bvs = (const float*)d_in[11];
    const float* Wvt = (const float*)d_in[12];
    const float* bvt = (const float*)d_in[13];
    const float* attn_bias = (const float*)d_in[14];
    float* out = (float*)d_out;

    cudaFuncSetAttribute(attn_mma,
        cudaFuncAttributeMaxDynamicSharedMemorySize, 98304);

    uint32_t* Xh; uint32_t* Xl; uint32_t* Wh; uint32_t* Wl;
    cudaGetSymbolAddress((void**)&Xh, g_Xh);
    cudaGetSymbolAddress((void**)&Xl, g_Xl);
    cudaGetSymbolAddress((void**)&Wh, g_Wh);
    cudaGetSymbolAddress((void**)&Wl, g_Wl);

    prep_split<<<dim3(64, 128), 256>>>(Xs, Xt, Xh, Xl);
    prep_split<<<dim3(8, 128), 256>>>(Wqs, Wqt, Wh, Wl);
    prep_split<<<dim3(8, 128), 256>>>(Wks, Wkt, Wh + 1048576, Wl + 1048576);
    prep_split<<<dim3(8, 128), 256>>>(Wvs, Wvt, Wh + 2097152, Wl + 2097152);

    dim3 gGrid(64, 24);
    qkv_gemm_v13<<<gGrid, 256>>>(bqs, bqt, bks, bkt, bvs, bvt);

    dim3 aGrid(16, B_ * H_);
    attn_mma<<<aGrid, 256, 98304>>>(attn_bias, out);
}